// round 4
// baseline (speedup 1.0000x reference)
#include <cuda_runtime.h>
#include <cuda_bf16.h>
#include <cstddef>

// Per-edge cosine similarity + sigmoid + straight-through threshold.
//   out[e] = let v = sigmoid(cos(f1,f2)/T) in (v <= 0.5 ? 0 : v)
//
// Two-kernel plan (both captured in one graph):
//  1) norm_kernel: rinv[n] = 1 / max(||emb[n]||, eps)   (per-NODE, 100k rows)
//  2) edge_kernel: dot(f1,f2) * rinv[i1] * rinv[i2] -> sigmoid -> threshold
// This removes 2/3 of the FMA work and 7/9 of the SHFLs from the hot
// per-edge path (R3 ncu showed issue-bound: issue=69%, L2 only 48%).

#define MAX_NODES (2*1024*1024)
__device__ float g_rinv[MAX_NODES];

static __device__ __forceinline__ float decode_scalar(const void* p) {
    if (p == nullptr) return 1.0f;
    int iv = *(const int*)p;
    if (iv > 0 && iv < (1 << 23)) return (float)iv;   // stored as int32
    return __int_as_float(iv);                        // stored as f32 bits
}

// 8 lanes per node: each lane 2 float4 (coalesced 256B row), 3-step shfl.
__global__ void __launch_bounds__(256) norm_kernel(
    const float4* __restrict__ emb, float* __restrict__ rinv, int N)
{
    int tid = blockIdx.x * blockDim.x + threadIdx.x;
    int nid = tid >> 3;
    int sub = tid & 7;
    if (nid >= N) return;

    const float4* a = emb + (size_t)nid * 16;
    float4 v0 = __ldg(&a[sub]);
    float4 v1 = __ldg(&a[sub + 8]);

    float n = v0.x*v0.x + v0.y*v0.y + v0.z*v0.z + v0.w*v0.w
            + v1.x*v1.x + v1.y*v1.y + v1.z*v1.z + v1.w*v1.w;

    #pragma unroll
    for (int m = 4; m > 0; m >>= 1)
        n += __shfl_xor_sync(0xFFFFFFFFu, n, m);

    if (sub == 0) {
        float d = fmaxf(sqrtf(n), 1e-6f);
        rinv[nid] = 1.0f / d;
    }
}

// 4 lanes per edge: each lane 4+4 float4 (full coalesced 256B per row,
// MLP=8), dot-only 2-step shfl reduction.
__global__ void __launch_bounds__(256) edge_kernel(
    const float4* __restrict__ emb,   // [N*16]
    const int*    __restrict__ ei,    // [2*E]
    const float*  __restrict__ rinv,  // [N]
    const void*   __restrict__ temp,
    float*        __restrict__ out,   // [E]
    int E)
{
    int tid = blockIdx.x * blockDim.x + threadIdx.x;
    int eid = tid >> 2;
    int sub = tid & 3;
    if (eid >= E) return;

    int i1 = __ldg(&ei[eid]);
    int i2 = __ldg(&ei[E + eid]);

    const float4* a = emb + (size_t)i1 * 16;
    const float4* b = emb + (size_t)i2 * 16;

    float4 a0 = __ldg(&a[sub]);
    float4 a1 = __ldg(&a[sub + 4]);
    float4 a2 = __ldg(&a[sub + 8]);
    float4 a3 = __ldg(&a[sub + 12]);
    float4 b0 = __ldg(&b[sub]);
    float4 b1 = __ldg(&b[sub + 4]);
    float4 b2 = __ldg(&b[sub + 8]);
    float4 b3 = __ldg(&b[sub + 12]);

    float dot = a0.x*b0.x + a0.y*b0.y + a0.z*b0.z + a0.w*b0.w
              + a1.x*b1.x + a1.y*b1.y + a1.z*b1.z + a1.w*b1.w
              + a2.x*b2.x + a2.y*b2.y + a2.z*b2.z + a2.w*b2.w
              + a3.x*b3.x + a3.y*b3.y + a3.z*b3.z + a3.w*b3.w;

    dot += __shfl_xor_sync(0xFFFFFFFFu, dot, 1);
    dot += __shfl_xor_sync(0xFFFFFFFFu, dot, 2);

    if (sub == 0) {
        float att = dot * __ldg(&rinv[i1]) * __ldg(&rinv[i2]);
        float T = decode_scalar(temp);
        float v = 1.0f / (1.0f + __expf(-att / T));
        out[eid] = (v <= 0.5f) ? 0.0f : v;
    }
}

extern "C" void kernel_launch(void* const* d_in, const int* in_sizes, int n_in,
                              void* d_out, int out_size)
{
    const float4* emb  = (const float4*)d_in[0];
    const int*    ei   = (const int*)d_in[1];
    const void*   temp = (n_in > 2) ? d_in[2] : nullptr;
    float*        out  = (float*)d_out;

    int N = in_sizes[0] / 64;   // node_embs has N*64 elements
    int E = in_sizes[1] / 2;    // edge_index has 2*E elements

    float* rinv = nullptr;
    cudaGetSymbolAddress((void**)&rinv, g_rinv);

    {
        int threads = 256;
        long long total = (long long)N * 8;
        int blocks = (int)((total + threads - 1) / threads);
        norm_kernel<<<blocks, threads>>>(emb, rinv, N);
    }
    {
        int threads = 256;
        long long total = (long long)E * 4;
        int blocks = (int)((total + threads - 1) / threads);
        edge_kernel<<<blocks, threads>>>(emb, ei, rinv, temp, out, E);
    }
}

// round 5
// speedup vs baseline: 1.6784x; 1.6784x over previous
#include <cuda_runtime.h>
#include <cuda_bf16.h>
#include <cstddef>

// Per-edge cosine similarity + sigmoid + straight-through threshold.
//   out[e] = let v = sigmoid(cos(f1,f2)/T) in (v <= 0.5 ? 0 : v)
//
// Plan (one graph, two kernels):
//  1) norm_kernel: rinv[n] = 1 / max(||emb[n]||, eps)          (100k nodes)
//  2) edge_kernel: dot(f1,f2)*rinv[i1]*rinv[i2] -> sigmoid -> threshold
//
// Geometry lesson from R3/R4 ncu:
//  - 8 lanes/edge => each LDG.128 covers one FULL 128B line per edge
//    (L1 wavefront-efficient; R3 showed L1=55.6%).
//  - 4 lanes/edge split each line across two instructions and doubled L1
//    wavefronts (R4: L1=91.5%, 117us). Never again.
//  - rinv precompute cuts per-edge FMAs 3x and shuffles 3x vs R3
//    (R3 was issue-bound at 69.4%).

#define MAX_NODES (2*1024*1024)
__device__ float g_rinv[MAX_NODES];

static __device__ __forceinline__ float decode_scalar(const void* p) {
    if (p == nullptr) return 1.0f;
    int iv = *(const int*)p;
    if (iv > 0 && iv < (1 << 23)) return (float)iv;   // stored as int32
    return __int_as_float(iv);                        // stored as f32 bits
}

// 8 lanes per node: each lane 2 float4 (full-line coalesced), 3-step shfl.
__global__ void __launch_bounds__(256) norm_kernel(
    const float4* __restrict__ emb, float* __restrict__ rinv, int N)
{
    int tid = blockIdx.x * blockDim.x + threadIdx.x;
    int nid = tid >> 3;
    int sub = tid & 7;
    if (nid >= N) return;

    const float4* a = emb + (size_t)nid * 16;
    float4 v0 = __ldg(&a[sub]);
    float4 v1 = __ldg(&a[sub + 8]);

    float n = v0.x*v0.x + v0.y*v0.y + v0.z*v0.z + v0.w*v0.w
            + v1.x*v1.x + v1.y*v1.y + v1.z*v1.z + v1.w*v1.w;

    #pragma unroll
    for (int m = 4; m > 0; m >>= 1)
        n += __shfl_xor_sync(0xFFFFFFFFu, n, m);

    if (sub == 0) {
        float d = fmaxf(sqrtf(n), 1e-6f);
        rinv[nid] = 1.0f / d;
    }
}

// 8 lanes per edge: each lane 2 float4 per endpoint (each LDG.128 covers a
// full 128B line of the row), dot-only 3-step shfl reduction.
__global__ void __launch_bounds__(256) edge_kernel(
    const float4* __restrict__ emb,   // [N*16]
    const int*    __restrict__ ei,    // [2*E]
    const float*  __restrict__ rinv,  // [N]
    const void*   __restrict__ temp,
    float*        __restrict__ out,   // [E]
    int E)
{
    int tid = blockIdx.x * blockDim.x + threadIdx.x;
    int eid = tid >> 3;
    int sub = tid & 7;
    if (eid >= E) return;

    int i1 = __ldg(&ei[eid]);
    int i2 = __ldg(&ei[E + eid]);

    const float4* a = emb + (size_t)i1 * 16;
    const float4* b = emb + (size_t)i2 * 16;

    float4 a0 = __ldg(&a[sub]);
    float4 a1 = __ldg(&a[sub + 8]);
    float4 b0 = __ldg(&b[sub]);
    float4 b1 = __ldg(&b[sub + 8]);

    float dot = a0.x*b0.x + a0.y*b0.y + a0.z*b0.z + a0.w*b0.w
              + a1.x*b1.x + a1.y*b1.y + a1.z*b1.z + a1.w*b1.w;

    #pragma unroll
    for (int m = 4; m > 0; m >>= 1)
        dot += __shfl_xor_sync(0xFFFFFFFFu, dot, m);

    if (sub == 0) {
        float att = dot * __ldg(&rinv[i1]) * __ldg(&rinv[i2]);
        float T = decode_scalar(temp);
        float v = 1.0f / (1.0f + __expf(-att / T));
        out[eid] = (v <= 0.5f) ? 0.0f : v;
    }
}

extern "C" void kernel_launch(void* const* d_in, const int* in_sizes, int n_in,
                              void* d_out, int out_size)
{
    const float4* emb  = (const float4*)d_in[0];
    const int*    ei   = (const int*)d_in[1];
    const void*   temp = (n_in > 2) ? d_in[2] : nullptr;
    float*        out  = (float*)d_out;

    int N = in_sizes[0] / 64;   // node_embs has N*64 elements
    int E = in_sizes[1] / 2;    // edge_index has 2*E elements

    float* rinv = nullptr;
    cudaGetSymbolAddress((void**)&rinv, g_rinv);

    {
        int threads = 256;
        long long total = (long long)N * 8;
        int blocks = (int)((total + threads - 1) / threads);
        norm_kernel<<<blocks, threads>>>(emb, rinv, N);
    }
    {
        int threads = 256;
        long long total = (long long)E * 8;
        int blocks = (int)((total + threads - 1) / threads);
        edge_kernel<<<blocks, threads>>>(emb, ei, rinv, temp, out, E);
    }
}